// round 2
// baseline (speedup 1.0000x reference)
#include <cuda_runtime.h>
#include <math.h>

#define Bdim 64
#define Tdim 512
#define Idim 1024
#define Hdim 1024
#define M_TOT (Bdim*Tdim)   /* 32768 */

/* ---- scratch (device globals: no allocation allowed) ---- */
__device__ float g_xw[(size_t)M_TOT * Hdim];       /* 128 MB: xw = x@W^T + bW */
__device__ float g_h3T[2][Hdim * Bdim];            /* h3 state, transposed [h][b], ping-pong */
__device__ unsigned g_count = 0;
__device__ volatile unsigned g_gen = 0;

/* ================= GEMM 1: xw[m][n] = sum_k x[m][k]*W[n][k] + bW[n] ================= */
#define BM 128
#define BN 128
#define BK 8

__global__ __launch_bounds__(256) void gemm_xw_kernel(
    const float* __restrict__ x, const float* __restrict__ W, const float* __restrict__ bW)
{
    __shared__ __align__(16) float As[BK][BM];
    __shared__ __align__(16) float Bs[BK][BN];

    const int tid = threadIdx.x;
    const int m0 = blockIdx.y * BM;
    const int n0 = blockIdx.x * BN;
    const int lr = tid >> 1;           /* 0..127 row within tile */
    const int lc = (tid & 1) * 4;      /* 0 or 4 : k offset */
    const int ty = tid >> 4;           /* 0..15 */
    const int tx = tid & 15;           /* 0..15 */

    float acc[8][8];
#pragma unroll
    for (int i = 0; i < 8; ++i)
#pragma unroll
        for (int j = 0; j < 8; ++j) acc[i][j] = 0.f;

    for (int k0 = 0; k0 < Idim; k0 += BK) {
        float4 av = *(const float4*)&x[(size_t)(m0 + lr) * Idim + k0 + lc];
        float4 bv = *(const float4*)&W[(size_t)(n0 + lr) * Idim + k0 + lc];
        As[lc + 0][lr] = av.x; As[lc + 1][lr] = av.y; As[lc + 2][lr] = av.z; As[lc + 3][lr] = av.w;
        Bs[lc + 0][lr] = bv.x; Bs[lc + 1][lr] = bv.y; Bs[lc + 2][lr] = bv.z; Bs[lc + 3][lr] = bv.w;
        __syncthreads();
#pragma unroll
        for (int kk = 0; kk < BK; ++kk) {
            float a[8], b[8];
            *(float4*)(a)     = *(const float4*)&As[kk][ty * 8];
            *(float4*)(a + 4) = *(const float4*)&As[kk][ty * 8 + 4];
            *(float4*)(b)     = *(const float4*)&Bs[kk][tx * 8];
            *(float4*)(b + 4) = *(const float4*)&Bs[kk][tx * 8 + 4];
#pragma unroll
            for (int i = 0; i < 8; ++i)
#pragma unroll
                for (int j = 0; j < 8; ++j)
                    acc[i][j] += a[i] * b[j];
        }
        __syncthreads();
    }

#pragma unroll
    for (int i = 0; i < 8; ++i) {
        const int m = m0 + ty * 8 + i;
#pragma unroll
        for (int j = 0; j < 8; j += 4) {
            const int n = n0 + tx * 8 + j;
            float4 bwv = *(const float4*)&bW[n];
            float4 o;
            o.x = acc[i][j + 0] + bwv.x;
            o.y = acc[i][j + 1] + bwv.y;
            o.z = acc[i][j + 2] + bwv.z;
            o.w = acc[i][j + 3] + bwv.w;
            *(float4*)&g_xw[(size_t)m * Hdim + n] = o;
        }
    }
}

/* ================= Persistent recurrence kernel ================= */
/* Grid: 32 col-groups (x) * 4 batch-groups (y) = 128 CTAs, 256 threads each.
   CTA tile: 16 batches x 32 output cols. U slice (32 rows x 1024) resident in SMEM.
   Per step: stage h3(t-1) [16 x 1024] into SMEM, split-K(8) fp32 GEMM, reduce,
   tanh(xw + .) epilogue, write out1 + next state, grid barrier. */
#define RB 16
#define RC 32
#define NBLK 128
#define US_STRIDE 36     /* 1024 rows x 36 floats (padded, 16B-aligned rows) */
#define H3_STRIDE 20     /* 1024 rows x 20 floats */
#define RED_STRIDE 520
#define SMEM_FLOATS (Hdim*US_STRIDE + Hdim*H3_STRIDE + 32)
#define SMEM_BYTES (SMEM_FLOATS * 4)

__device__ __forceinline__ void grid_barrier(unsigned target)
{
    __syncthreads();
    if (threadIdx.x == 0) {
        __threadfence();
        unsigned prev = atomicAdd(&g_count, 1u);
        if (prev == NBLK - 1) {
            g_count = 0;
            __threadfence();
            g_gen = target;                 /* release */
        } else {
            while (g_gen < target) { __nanosleep(40); }
            __threadfence();                /* acquire */
        }
    }
    __syncthreads();
}

__global__ __launch_bounds__(256) void rnn_steps_kernel(
    const float* __restrict__ U, const float* __restrict__ bU, float* __restrict__ out)
{
    extern __shared__ __align__(16) float sm[];
    float* Us  = sm;                         /* [1024][36] : Us[k*36 + c] = U[c0+c][k] */
    float* h3s = sm + Hdim * US_STRIDE;      /* [1024][20] : h3s[k*20 + b] = h3[b0+b][k] */
    float* red = h3s;                        /* aliased: 8 x 520 floats, used post-GEMM */
    float* bUs = h3s + Hdim * H3_STRIDE;     /* [32] */

    const int tid = threadIdx.x;
    const int c0 = blockIdx.x * RC;
    const int b0 = blockIdx.y * RB;
    float* out1 = out;
    float* out2 = out + (size_t)M_TOT * Hdim;

    /* Load U slice, transposed into padded SMEM (one-time) */
    for (int i = tid; i < RC * (Hdim / 4); i += 256) {
        const int c  = i >> 8;         /* 0..31 */
        const int kq = i & 255;        /* float4 index along k */
        float4 v = *(const float4*)&U[(size_t)(c0 + c) * Hdim + 4 * kq];
        Us[(4 * kq + 0) * US_STRIDE + c] = v.x;
        Us[(4 * kq + 1) * US_STRIDE + c] = v.y;
        Us[(4 * kq + 2) * US_STRIDE + c] = v.z;
        Us[(4 * kq + 3) * US_STRIDE + c] = v.w;
    }
    if (tid < RC) bUs[tid] = bU[c0 + tid];

    /* Barrier base generation (persists across graph replays). All reads happen
       before this CTA's first arrival, hence before any release -> consistent. */
    const unsigned base = g_gen;
    __syncthreads();

    /* ---- t = 0 : h3 = tanh(xw[:,0,:]) ---- */
#pragma unroll
    for (int u = 0; u < 2; ++u) {
        const int o = tid + u * 256;
        const int bl = o >> 5, cl = o & 31;
        const int b = b0 + bl, c = c0 + cl;
        const size_t idx = ((size_t)b * Tdim + 0) * Hdim + c;
        const float h = tanhf(g_xw[idx]);
        out1[idx] = h;
        g_h3T[0][c * Bdim + b] = h;
    }
    unsigned nbar = 0;
    grid_barrier(base + (++nbar));

    const int ks   = tid >> 5;       /* k-split 0..7, 128 k each (whole warp same ks) */
    const int lane = tid & 31;
    const int bq   = lane >> 3;      /* 0..3 -> 4 batches */
    const int cq   = lane & 7;       /* 0..7 -> 4 cols   */

    for (int t = 1; t < Tdim; ++t) {
        /* stage h3(t-1): global [h][64] -> smem [h][20] */
        const float* src = g_h3T[(t - 1) & 1];
        for (int i = tid; i < Hdim * (RB / 4); i += 256) {
            const int k = i >> 2;
            const int b4 = (i & 3) * 4;
            float4 v = *(const float4*)&src[k * Bdim + b0 + b4];
            *(float4*)&h3s[k * H3_STRIDE + b4] = v;
        }
        __syncthreads();

        /* split-K fp32 GEMM: acc[i][j] = sum_k h3[b0+4bq+i][k]*U[c0+4cq+j][k] */
        float acc[4][4];
#pragma unroll
        for (int i = 0; i < 4; ++i)
#pragma unroll
            for (int j = 0; j < 4; ++j) acc[i][j] = 0.f;

        const float* hp = h3s + (ks * 128) * H3_STRIDE + bq * 4;
        const float* up = Us  + (ks * 128) * US_STRIDE + cq * 4;
#pragma unroll 8
        for (int kk = 0; kk < 128; ++kk) {
            float4 hv = *(const float4*)hp; hp += H3_STRIDE;
            float4 uv = *(const float4*)up; up += US_STRIDE;
            float ha[4] = {hv.x, hv.y, hv.z, hv.w};
            float ua[4] = {uv.x, uv.y, uv.z, uv.w};
#pragma unroll
            for (int i = 0; i < 4; ++i)
#pragma unroll
                for (int j = 0; j < 4; ++j)
                    acc[i][j] += ha[i] * ua[j];
        }
        __syncthreads();   /* all h3s reads done: red may alias */

        {
            float* rp = red + ks * RED_STRIDE + (bq * 4) * 32 + cq * 4;
#pragma unroll
            for (int i = 0; i < 4; ++i)
#pragma unroll
                for (int j = 0; j < 4; ++j)
                    rp[i * 32 + j] = acc[i][j];
        }
        __syncthreads();

        /* reduce over k-split + epilogue */
#pragma unroll
        for (int u = 0; u < 2; ++u) {
            const int o = tid + u * 256;
            float s = 0.f;
#pragma unroll
            for (int r = 0; r < 8; ++r) s += red[r * RED_STRIDE + o];
            const int bl = o >> 5, cl = o & 31;
            const int b = b0 + bl, c = c0 + cl;
            s += bUs[cl];
            const size_t idx = ((size_t)b * Tdim + t) * Hdim + c;
            const float h = tanhf(g_xw[idx] + s);
            out1[idx] = h;
            g_h3T[t & 1][c * Bdim + b] = h;
            if (t == Tdim - 1) out2[(size_t)b * Hdim + c] = h;
        }
        if (t < Tdim - 1) grid_barrier(base + (++nbar));
    }
}

/* ================= launch ================= */
extern "C" void kernel_launch(void* const* d_in, const int* in_sizes, int n_in,
                              void* d_out, int out_size)
{
    const float* x  = (const float*)d_in[0];
    const float* W  = (const float*)d_in[1];
    const float* bW = (const float*)d_in[2];
    const float* U  = (const float*)d_in[3];
    const float* bU = (const float*)d_in[4];
    float* out = (float*)d_out;

    gemm_xw_kernel<<<dim3(Hdim / BN, M_TOT / BM), 256>>>(x, W, bW);

    cudaFuncSetAttribute(rnn_steps_kernel,
                         cudaFuncAttributeMaxDynamicSharedMemorySize, SMEM_BYTES);
    rnn_steps_kernel<<<dim3(32, 4), 256, SMEM_BYTES>>>(U, bU, out);
}

// round 4
// speedup vs baseline: 1.1104x; 1.1104x over previous
#include <cuda_runtime.h>
#include <math.h>

#define Bdim 64
#define Tdim 512
#define Idim 1024
#define Hdim 1024
#define M_TOT (Bdim*Tdim)   /* 32768 */

typedef unsigned long long u64;

/* ---- packed fp32x2 helpers (FFMA2) ---- */
__device__ __forceinline__ u64 pk2(float x, float y) {
    u64 r; asm("mov.b64 %0, {%1, %2};" : "=l"(r) : "f"(x), "f"(y)); return r;
}
__device__ __forceinline__ void fma2(u64& d, u64 a, u64 b) {
    asm("fma.rn.f32x2 %0, %1, %2, %0;" : "+l"(d) : "l"(a), "l"(b));
}
__device__ __forceinline__ float2 up2(u64 v) {
    float2 r; asm("mov.b64 {%0, %1}, %2;" : "=f"(r.x), "=f"(r.y) : "l"(v)); return r;
}

/* ---- scratch (device globals: no allocation allowed) ---- */
__device__ float g_xw[(size_t)M_TOT * Hdim];       /* 128 MB: xw = x@W^T + bW */
__device__ float g_h3T[2][Hdim * Bdim];            /* h3 state, transposed [h][b], ping-pong */
__device__ unsigned g_cnt4[4][32];                 /* per-batch-group barrier counters (padded) */
__device__ volatile unsigned g_gen4[4][32];        /* per-batch-group generation */

/* ================= GEMM 1: xw[m][n] = sum_k x[m][k]*W[n][k] + bW[n] =================
   128x128 block, BK=16, 256 threads, double-buffered SMEM, fp32x2 math. */
__global__ __launch_bounds__(256) void gemm_xw_kernel(
    const float* __restrict__ x, const float* __restrict__ W, const float* __restrict__ bW)
{
    __shared__ __align__(16) float As[2][16][132];
    __shared__ __align__(16) float Bs[2][16][132];

    const int tid = threadIdx.x;
    const int m0 = blockIdx.y * 128;
    const int n0 = blockIdx.x * 128;
    const int kc = (tid & 3) * 4;      /* k offset (float4) within BK tile */
    const int mr = tid >> 2;           /* 0..63 row */
    const int ty = tid >> 4;           /* 0..15 : rows ty*8..+7 */
    const int tx = tid & 15;           /* cols tx*4..+3 and 64+tx*4..+3 */

    const float* xg  = x + (size_t)(m0 + mr) * Idim + kc;
    const float* xg2 = xg + (size_t)64 * Idim;
    const float* wg  = W + (size_t)(n0 + mr) * Idim + kc;
    const float* wg2 = wg + (size_t)64 * Idim;

    float4 xa = *(const float4*)xg;
    float4 xb = *(const float4*)xg2;
    float4 wa = *(const float4*)wg;
    float4 wb = *(const float4*)wg2;

    As[0][kc + 0][mr] = xa.x; As[0][kc + 1][mr] = xa.y; As[0][kc + 2][mr] = xa.z; As[0][kc + 3][mr] = xa.w;
    As[0][kc + 0][64 + mr] = xb.x; As[0][kc + 1][64 + mr] = xb.y; As[0][kc + 2][64 + mr] = xb.z; As[0][kc + 3][64 + mr] = xb.w;
    Bs[0][kc + 0][mr] = wa.x; Bs[0][kc + 1][mr] = wa.y; Bs[0][kc + 2][mr] = wa.z; Bs[0][kc + 3][mr] = wa.w;
    Bs[0][kc + 0][64 + mr] = wb.x; Bs[0][kc + 1][64 + mr] = wb.y; Bs[0][kc + 2][64 + mr] = wb.z; Bs[0][kc + 3][64 + mr] = wb.w;
    __syncthreads();

    u64 acc[8][4];
#pragma unroll
    for (int i = 0; i < 8; ++i)
#pragma unroll
        for (int j = 0; j < 4; ++j) acc[i][j] = 0ULL;

    for (int t = 0; t < 64; ++t) {
        if (t < 63) {
            const int off = (t + 1) * 16;
            xa = *(const float4*)(xg + off);
            xb = *(const float4*)(xg2 + off);
            wa = *(const float4*)(wg + off);
            wb = *(const float4*)(wg2 + off);
        }
        const int p = t & 1;
#pragma unroll
        for (int k = 0; k < 16; ++k) {
            float a[8];
            *(float4*)(a)     = *(const float4*)&As[p][k][ty * 8];
            *(float4*)(a + 4) = *(const float4*)&As[p][k][ty * 8 + 4];
            float4 b0 = *(const float4*)&Bs[p][k][tx * 4];
            float4 b1 = *(const float4*)&Bs[p][k][64 + tx * 4];
            u64 ub0 = pk2(b0.x, b0.y), ub1 = pk2(b0.z, b0.w);
            u64 ub2 = pk2(b1.x, b1.y), ub3 = pk2(b1.z, b1.w);
#pragma unroll
            for (int i = 0; i < 8; ++i) {
                u64 ai = pk2(a[i], a[i]);
                fma2(acc[i][0], ai, ub0);
                fma2(acc[i][1], ai, ub1);
                fma2(acc[i][2], ai, ub2);
                fma2(acc[i][3], ai, ub3);
            }
        }
        if (t < 63) {
            const int q = p ^ 1;
            As[q][kc + 0][mr] = xa.x; As[q][kc + 1][mr] = xa.y; As[q][kc + 2][mr] = xa.z; As[q][kc + 3][mr] = xa.w;
            As[q][kc + 0][64 + mr] = xb.x; As[q][kc + 1][64 + mr] = xb.y; As[q][kc + 2][64 + mr] = xb.z; As[q][kc + 3][64 + mr] = xb.w;
            Bs[q][kc + 0][mr] = wa.x; Bs[q][kc + 1][mr] = wa.y; Bs[q][kc + 2][mr] = wa.z; Bs[q][kc + 3][mr] = wa.w;
            Bs[q][kc + 0][64 + mr] = wb.x; Bs[q][kc + 1][64 + mr] = wb.y; Bs[q][kc + 2][64 + mr] = wb.z; Bs[q][kc + 3][64 + mr] = wb.w;
            __syncthreads();
        }
    }

    /* epilogue */
    const float4 bw0 = *(const float4*)&bW[n0 + tx * 4];
    const float4 bw1 = *(const float4*)&bW[n0 + 64 + tx * 4];
#pragma unroll
    for (int i = 0; i < 8; ++i) {
        const int m = m0 + ty * 8 + i;
        float2 p0 = up2(acc[i][0]), p1 = up2(acc[i][1]);
        float2 p2 = up2(acc[i][2]), p3 = up2(acc[i][3]);
        float4 o0, o1;
        o0.x = p0.x + bw0.x; o0.y = p0.y + bw0.y; o0.z = p1.x + bw0.z; o0.w = p1.y + bw0.w;
        o1.x = p2.x + bw1.x; o1.y = p2.y + bw1.y; o1.z = p3.x + bw1.z; o1.w = p3.y + bw1.w;
        *(float4*)&g_xw[(size_t)m * Hdim + n0 + tx * 4] = o0;
        *(float4*)&g_xw[(size_t)m * Hdim + n0 + 64 + tx * 4] = o1;
    }
}

/* ================= Persistent recurrence kernel =================
   Grid (32,4) = 128 CTAs, 512 threads. CTA tile: 16 batches x 32 cols.
   Batch groups (blockIdx.y) are fully independent -> 32-CTA group barriers.
   U slice resident in SMEM; split-K 16; fp32x2 inner math. */
#define RB 16
#define RC 32
#define GRP 32             /* CTAs per barrier group */
#define RTHREADS 512
#define KCHUNK 64          /* 1024 / 16 k-splits */
#define US_STRIDE 36
#define H3_STRIDE 20
#define RED_STRIDE 520
#define SMEM_FLOATS (Hdim*US_STRIDE + Hdim*H3_STRIDE + 32)
#define SMEM_BYTES (SMEM_FLOATS * 4)

__device__ __forceinline__ void group_barrier(int bg, unsigned target)
{
    __syncthreads();
    if (threadIdx.x == 0) {
        __threadfence();
        unsigned prev = atomicAdd(&g_cnt4[bg][0], 1u);
        if (prev == GRP - 1) {
            g_cnt4[bg][0] = 0;
            __threadfence();
            g_gen4[bg][0] = target;            /* release */
        } else {
            while ((int)(g_gen4[bg][0] - target) < 0) {}
            __threadfence();                   /* acquire */
        }
    }
    __syncthreads();
}

__global__ __launch_bounds__(RTHREADS) void rnn_steps_kernel(
    const float* __restrict__ U, const float* __restrict__ bU, float* __restrict__ out)
{
    extern __shared__ __align__(16) float sm[];
    float* Us  = sm;                         /* [1024][36] : Us[k*36 + c] = U[c0+c][k] */
    float* h3s = sm + Hdim * US_STRIDE;      /* [1024][20] : h3s[k*20 + b] */
    float* red = h3s;                        /* aliased: 16 x 520 floats */
    float* bUs = h3s + Hdim * H3_STRIDE;     /* [32] */

    const int tid = threadIdx.x;
    const int c0 = blockIdx.x * RC;
    const int bg = blockIdx.y;
    const int b0 = bg * RB;
    float* out1 = out;
    float* out2 = out + (size_t)M_TOT * Hdim;

    /* Load U slice transposed (one-time): 32 cols x 1024 k */
    for (int i = tid; i < RC * (Hdim / 4); i += RTHREADS) {
        const int c  = i >> 8;
        const int kq = i & 255;
        float4 v = *(const float4*)&U[(size_t)(c0 + c) * Hdim + 4 * kq];
        Us[(4 * kq + 0) * US_STRIDE + c] = v.x;
        Us[(4 * kq + 1) * US_STRIDE + c] = v.y;
        Us[(4 * kq + 2) * US_STRIDE + c] = v.z;
        Us[(4 * kq + 3) * US_STRIDE + c] = v.w;
    }
    if (tid < RC) bUs[tid] = bU[c0 + tid];

    /* barrier base generation (persists across graph replays) */
    const unsigned base = g_gen4[bg][0];
    __syncthreads();

    const int ob = tid >> 5;       /* output batch-lane 0..15 */
    const int oc = tid & 31;       /* output col-lane  0..31 */

    /* ---- t = 0 ---- */
    {
        const size_t idx = ((size_t)(b0 + ob) * Tdim + 0) * Hdim + (c0 + oc);
        const float h = tanhf(g_xw[idx]);
        out1[idx] = h;
        g_h3T[0][(c0 + oc) * Bdim + (b0 + ob)] = h;
    }
    unsigned nbar = 0;
    group_barrier(bg, base + (++nbar));

    const int ks   = tid >> 5;     /* k-split 0..15 (whole warp) */
    const int lane = tid & 31;
    const int bq   = lane >> 3;    /* 4 batches */
    const int cq   = lane & 7;     /* 4 cols */

    for (int t = 1; t < Tdim; ++t) {
        /* prefetch xw for the epilogue (hidden behind staging + GEMM) */
        const size_t oidx = ((size_t)(b0 + ob) * Tdim + t) * Hdim + (c0 + oc);
        const float xwv = __ldg(&g_xw[oidx]);

        /* stage h3(t-1): global [h][64] -> smem [h][20]  (4096 f4 / 512 thr) */
        const float* src = g_h3T[(t - 1) & 1];
#pragma unroll
        for (int u = 0; u < 8; ++u) {
            const int i = tid + u * RTHREADS;
            const int k = i >> 2;
            const int b4 = (i & 3) * 4;
            float4 v = *(const float4*)&src[k * Bdim + b0 + b4];
            *(float4*)&h3s[k * H3_STRIDE + b4] = v;
        }
        __syncthreads();

        /* split-K fp32x2 GEMM */
        u64 acc[4][2];
#pragma unroll
        for (int i = 0; i < 4; ++i) { acc[i][0] = 0ULL; acc[i][1] = 0ULL; }

        const float* hp = h3s + (ks * KCHUNK) * H3_STRIDE + bq * 4;
        const float* up = Us  + (ks * KCHUNK) * US_STRIDE + cq * 4;
#pragma unroll 8
        for (int kk = 0; kk < KCHUNK; ++kk) {
            float4 hv = *(const float4*)hp; hp += H3_STRIDE;
            float4 uv = *(const float4*)up; up += US_STRIDE;
            u64 ub0 = pk2(uv.x, uv.y), ub1 = pk2(uv.z, uv.w);
            u64 a0 = pk2(hv.x, hv.x); fma2(acc[0][0], a0, ub0); fma2(acc[0][1], a0, ub1);
            u64 a1 = pk2(hv.y, hv.y); fma2(acc[1][0], a1, ub0); fma2(acc[1][1], a1, ub1);
            u64 a2 = pk2(hv.z, hv.z); fma2(acc[2][0], a2, ub0); fma2(acc[2][1], a2, ub1);
            u64 a3 = pk2(hv.w, hv.w); fma2(acc[3][0], a3, ub0); fma2(acc[3][1], a3, ub1);
        }
        __syncthreads();   /* h3s reads done: red may alias */

        {
            float* rp = red + ks * RED_STRIDE + (bq * 4) * 32 + cq * 4;
#pragma unroll
            for (int i = 0; i < 4; ++i) {
                float2 p0 = up2(acc[i][0]), p1 = up2(acc[i][1]);
                rp[i * 32 + 0] = p0.x; rp[i * 32 + 1] = p0.y;
                rp[i * 32 + 2] = p1.x; rp[i * 32 + 3] = p1.y;
            }
        }
        __syncthreads();

        /* reduce over 16 k-splits + epilogue (1 output per thread) */
        float s = 0.f;
#pragma unroll
        for (int r = 0; r < 16; ++r) s += red[r * RED_STRIDE + tid];
        s += bUs[oc];
        const float h = tanhf(xwv + s);
        out1[oidx] = h;
        g_h3T[t & 1][(c0 + oc) * Bdim + (b0 + ob)] = h;
        if (t == Tdim - 1) out2[(size_t)(b0 + ob) * Hdim + (c0 + oc)] = h;

        if (t < Tdim - 1) group_barrier(bg, base + (++nbar));
    }
}

/* ================= launch ================= */
extern "C" void kernel_launch(void* const* d_in, const int* in_sizes, int n_in,
                              void* d_out, int out_size)
{
    const float* x  = (const float*)d_in[0];
    const float* W  = (const float*)d_in[1];
    const float* bW = (const float*)d_in[2];
    const float* U  = (const float*)d_in[3];
    const float* bU = (const float*)d_in[4];
    float* out = (float*)d_out;

    gemm_xw_kernel<<<dim3(Hdim / 128, M_TOT / 128), 256>>>(x, W, bW);

    cudaFuncSetAttribute(rnn_steps_kernel,
                         cudaFuncAttributeMaxDynamicSharedMemorySize, SMEM_BYTES);
    rnn_steps_kernel<<<dim3(32, 4), RTHREADS, SMEM_BYTES>>>(U, bU, out);
}

// round 10
// speedup vs baseline: 2.3161x; 2.0859x over previous
#include <cuda_runtime.h>
#include <cuda_bf16.h>
#include <math.h>
#include <stdint.h>

#define Bdim 64
#define Tdim 512
#define Idim 1024
#define Hdim 1024
#define M_TOT (Bdim*Tdim)   /* 32768 */

typedef unsigned long long u64;

/* ================= PTX helpers (all base-sm_103-safe: sm_80 era) ================= */
__device__ __forceinline__ uint32_t smem_u32(const void* p) {
    uint32_t a;
    asm("{ .reg .u64 t; cvta.to.shared.u64 t, %1; cvt.u32.u64 %0, t; }" : "=r"(a) : "l"(p));
    return a;
}
#define LDSM_X4(r, addr) \
    asm volatile("ldmatrix.sync.aligned.m8n8.x4.shared.b16 {%0,%1,%2,%3}, [%4];" \
        : "=r"((r)[0]), "=r"((r)[1]), "=r"((r)[2]), "=r"((r)[3]) : "r"(addr))
#define LDSM_X2(r, addr) \
    asm volatile("ldmatrix.sync.aligned.m8n8.x2.shared.b16 {%0,%1}, [%2];" \
        : "=r"((r)[0]), "=r"((r)[1]) : "r"(addr))
__device__ __forceinline__ void mma16816(float* c, const uint32_t* a, const uint32_t* b) {
    asm volatile(
        "mma.sync.aligned.m16n8k16.row.col.f32.bf16.bf16.f32 "
        "{%0,%1,%2,%3}, {%4,%5,%6,%7}, {%8,%9}, {%0,%1,%2,%3};"
        : "+f"(c[0]), "+f"(c[1]), "+f"(c[2]), "+f"(c[3])
        : "r"(a[0]), "r"(a[1]), "r"(a[2]), "r"(a[3]), "r"(b[0]), "r"(b[1]));
}
#define CP_ASYNC16(dst, src) \
    asm volatile("cp.async.cg.shared.global [%0], [%1], 16;" :: "r"(dst), "l"(src))
#define CP_COMMIT() asm volatile("cp.async.commit_group;" ::: "memory")
#define CP_WAIT(N)  asm volatile("cp.async.wait_group %0;" :: "n"(N) : "memory")

/* ---- scratch (device globals: no allocation allowed) ---- */
__device__ float g_xw[(size_t)M_TOT * Hdim];              /* 128 MB */
__device__ __nv_bfloat16 g_xhi[(size_t)M_TOT * Idim];     /* 64 MB */
__device__ __nv_bfloat16 g_xlo[(size_t)M_TOT * Idim];     /* 64 MB */
__device__ __nv_bfloat16 g_whi[(size_t)Hdim * Idim];
__device__ __nv_bfloat16 g_wlo[(size_t)Hdim * Idim];
__device__ __nv_bfloat16 g_uhi[(size_t)Hdim * Hdim];
__device__ __nv_bfloat16 g_ulo[(size_t)Hdim * Hdim];
__device__ __nv_bfloat16 g_hhi[2][Bdim * Hdim];           /* h3 state hi, ping-pong */
__device__ __nv_bfloat16 g_hlo[2][Bdim * Hdim];           /* h3 state lo */
__device__ unsigned g_cnt4[4][32];
__device__ volatile unsigned g_gen4[4][32];

/* ================= fp32 -> bf16 hi/lo split ================= */
__global__ __launch_bounds__(256) void cvt_split_kernel(
    const float* __restrict__ src, int which, int n4)
{
    __nv_bfloat16 *hi, *lo;
    if (which == 0)      { hi = g_xhi; lo = g_xlo; }
    else if (which == 1) { hi = g_whi; lo = g_wlo; }
    else                 { hi = g_uhi; lo = g_ulo; }
    for (int i = blockIdx.x * 256 + threadIdx.x; i < n4; i += gridDim.x * 256) {
        float4 v = ((const float4*)src)[i];
        __nv_bfloat16 h0 = __float2bfloat16_rn(v.x);
        __nv_bfloat16 h1 = __float2bfloat16_rn(v.y);
        __nv_bfloat16 h2 = __float2bfloat16_rn(v.z);
        __nv_bfloat16 h3 = __float2bfloat16_rn(v.w);
        __nv_bfloat16 l0 = __float2bfloat16_rn(v.x - __bfloat162float(h0));
        __nv_bfloat16 l1 = __float2bfloat16_rn(v.y - __bfloat162float(h1));
        __nv_bfloat16 l2 = __float2bfloat16_rn(v.z - __bfloat162float(h2));
        __nv_bfloat16 l3 = __float2bfloat16_rn(v.w - __bfloat162float(h3));
        ((__nv_bfloat162*)hi)[2 * i + 0] = __halves2bfloat162(h0, h1);
        ((__nv_bfloat162*)hi)[2 * i + 1] = __halves2bfloat162(h2, h3);
        ((__nv_bfloat162*)lo)[2 * i + 0] = __halves2bfloat162(l0, l1);
        ((__nv_bfloat162*)lo)[2 * i + 1] = __halves2bfloat162(l2, l3);
    }
}

/* ================= GEMM1: xw = x@W^T + bW  (bf16x3 HMMA) =================
   CTA 128x128, 256 thr (8 warps = 2m x 4n, warp tile 64x32), K-chunk 64,
   cp.async double buffer. SMEM stride 72 bf16 (144B == 16 mod 128: conflict-free). */
#define GSK 72
#define GT_B (128 * GSK * 2)            /* 18432 B per tile array */
#define GBUF_B (4 * GT_B)               /* Ahi,Alo,Bhi,Blo = 73728 B */
#define GEMM_SMEM (2 * GBUF_B)          /* 147456 B */

__device__ __forceinline__ void g1_load_chunk(
    uint32_t sbuf, int tid, int m0, int n0, int it)
{
    const __nv_bfloat16* srcs[4] = {
        g_xhi + (size_t)m0 * Idim, g_xlo + (size_t)m0 * Idim,
        g_whi + (size_t)n0 * Idim, g_wlo + (size_t)n0 * Idim };
#pragma unroll
    for (int arr = 0; arr < 4; ++arr) {
        const __nv_bfloat16* s = srcs[arr] + it * 64;
#pragma unroll
        for (int u = 0; u < 4; ++u) {
            const int i = tid + u * 256;       /* 0..1023 */
            const int r = i >> 3, kq = i & 7;
            CP_ASYNC16(sbuf + arr * GT_B + (r * GSK + kq * 8) * 2,
                       (const char*)(s + (size_t)r * Idim + kq * 8));
        }
    }
}

__global__ __launch_bounds__(256, 1) void gemm_xw_hmma(const float* __restrict__ bW)
{
    extern __shared__ __align__(16) char gsm[];
    const uint32_t sb = smem_u32(gsm);
    const int tid = threadIdx.x;
    const int l = tid & 31, wid = tid >> 5;
    const int wm = wid >> 2, wn = wid & 3;
    const int n0 = blockIdx.x * 128;
    const int m0 = blockIdx.y * 128;

    /* per-lane fragment address terms */
    const int ra = wm * 64 + (l % 16);
    const int ca = (l >> 4) * 8;
    const int rb = wn * 32 + (l & 7);
    const int cb = ((l % 16) >> 3) * 8;

    float C[4][4][4];
#pragma unroll
    for (int a = 0; a < 4; ++a)
#pragma unroll
        for (int b = 0; b < 4; ++b)
#pragma unroll
            for (int c = 0; c < 4; ++c) C[a][b][c] = 0.f;

    g1_load_chunk(sb, tid, m0, n0, 0);
    CP_COMMIT();

    for (int it = 0; it < 16; ++it) {
        if (it < 15) {
            g1_load_chunk(sb + ((it + 1) & 1) * GBUF_B, tid, m0, n0, it + 1);
            CP_COMMIT();
            CP_WAIT(1);
        } else {
            CP_WAIT(0);
        }
        __syncthreads();

        const uint32_t buf = sb + (it & 1) * GBUF_B;
        const uint32_t aBaseHi = buf + (ra * GSK + ca) * 2;
        const uint32_t aBaseLo = aBaseHi + GT_B;
        const uint32_t bBaseHi = buf + 2 * GT_B + (rb * GSK + cb) * 2;
        const uint32_t bBaseLo = bBaseHi + GT_B;

#pragma unroll
        for (int s = 0; s < 4; ++s) {
            uint32_t ah[4][4], al[4][4], bh[4][2], bl[4][2];
#pragma unroll
            for (int mi = 0; mi < 4; ++mi) {
                LDSM_X4(ah[mi], aBaseHi + (mi * 16 * GSK + s * 16) * 2);
                LDSM_X4(al[mi], aBaseLo + (mi * 16 * GSK + s * 16) * 2);
            }
#pragma unroll
            for (int nj = 0; nj < 4; ++nj) {
                LDSM_X2(bh[nj], bBaseHi + (nj * 8 * GSK + s * 16) * 2);
                LDSM_X2(bl[nj], bBaseLo + (nj * 8 * GSK + s * 16) * 2);
            }
#pragma unroll
            for (int mi = 0; mi < 4; ++mi)
#pragma unroll
                for (int nj = 0; nj < 4; ++nj) {
                    mma16816(C[mi][nj], ah[mi], bh[nj]);
                    mma16816(C[mi][nj], ah[mi], bl[nj]);
                    mma16816(C[mi][nj], al[mi], bh[nj]);
                }
        }
        __syncthreads();
    }

    /* epilogue: direct store + bW */
    const int g = l >> 2, tig = l & 3;
#pragma unroll
    for (int mi = 0; mi < 4; ++mi)
#pragma unroll
        for (int nj = 0; nj < 4; ++nj) {
            const int row = m0 + wm * 64 + mi * 16 + g;
            const int col = n0 + wn * 32 + nj * 8 + 2 * tig;
            const float2 bw = *(const float2*)&bW[col];
            float2 v0, v1;
            v0.x = C[mi][nj][0] + bw.x; v0.y = C[mi][nj][1] + bw.y;
            v1.x = C[mi][nj][2] + bw.x; v1.y = C[mi][nj][3] + bw.y;
            *(float2*)&g_xw[(size_t)row * Hdim + col] = v0;
            *(float2*)&g_xw[(size_t)(row + 8) * Hdim + col] = v1;
        }
}

/* ================= Persistent recurrence (bf16x3 HMMA) =================
   Grid (32 col-groups, 4 batch-groups) = 128 CTAs, 512 thr (16 warps).
   CTA tile: 16 batches x 32 cols. U hi/lo slice resident in SMEM.
   Each warp: K-split of 64 (4 k16-steps), 48 HMMA/step; SMEM reduce. */
#define RB 16
#define RC 32
#define GRP 32
#define RTHREADS 512
#define SK 1032                          /* smem k-stride in bf16 (2064B == 16 mod 128) */
#define UHI_OFF 0
#define ULO_OFF (RC * SK * 2)            /* 66048 */
#define HHI_OFF (2 * RC * SK * 2)        /* 132096 */
#define HLO_OFF (HHI_OFF + RB * SK * 2)  /* 165120 */
#define BU_OFF  (HLO_OFF + RB * SK * 2)  /* 198144 */
#define RNN_SMEM (BU_OFF + 256)
#define RST 34                           /* reduce row stride, floats */
#define RWB (16 * RST)                   /* per-warp reduce block = 544 floats */

__device__ __forceinline__ void group_barrier(int bg, unsigned target)
{
    __syncthreads();
    if (threadIdx.x == 0) {
        __threadfence();
        unsigned prev = atomicAdd(&g_cnt4[bg][0], 1u);
        if (prev == GRP - 1) {
            g_cnt4[bg][0] = 0;
            __threadfence();
            g_gen4[bg][0] = target;
        } else {
            while ((int)(g_gen4[bg][0] - target) < 0) {}
            __threadfence();
        }
    }
    __syncthreads();
}

__global__ __launch_bounds__(RTHREADS, 1) void rnn_steps_hmma(
    const float* __restrict__ bU, float* __restrict__ out)
{
    extern __shared__ __align__(16) char rsm[];
    const uint32_t sb = smem_u32(rsm);
    float* bUs = (float*)(rsm + BU_OFF);
    float* red = (float*)(rsm + HHI_OFF);   /* aliases H region post-MMA */

    const int tid = threadIdx.x;
    const int l = tid & 31, w = tid >> 5;
    const int c0 = blockIdx.x * RC;
    const int bg = blockIdx.y;
    const int b0 = bg * RB;
    float* out1 = out;
    float* out2 = out + (size_t)M_TOT * Hdim;

    /* one-time: load U hi/lo slice [32 n][1024 k] into padded SMEM */
#pragma unroll
    for (int u = 0; u < 16; ++u) {
        const int i = tid + u * RTHREADS;      /* 0..8191 */
        const int arr = i >> 12, rem = i & 4095;
        const int r = rem >> 7, kq = rem & 127;
        const __nv_bfloat16* s = (arr ? g_ulo : g_uhi) + (size_t)(c0 + r) * Hdim + kq * 8;
        uint4 v = *(const uint4*)s;
        *(uint4*)(rsm + (arr ? ULO_OFF : UHI_OFF) + (r * SK + kq * 8) * 2) = v;
    }
    if (tid < RC) bUs[tid] = bU[c0 + tid];

    const unsigned base = g_gen4[bg][0];
    __syncthreads();

    const int ob = tid >> 5;      /* output batch 0..15 */
    const int oc = tid & 31;      /* output col   0..31 */
    const int g = l >> 2, tig = l & 3;

    /* per-lane fragment address bases */
    const uint32_t aHiB = sb + HHI_OFF + ((l % 16) * SK + (l >> 4) * 8 + w * 64) * 2;
    const uint32_t aLoB = aHiB + (HLO_OFF - HHI_OFF);
    const uint32_t bHiB = sb + UHI_OFF + ((l & 7) * SK + ((l % 16) >> 3) * 8 + w * 64) * 2;
    const uint32_t bLoB = bHiB + ULO_OFF;

    /* ---- t = 0 : h = tanh(xw) ---- */
    {
        const size_t idx = ((size_t)(b0 + ob) * Tdim + 0) * Hdim + (c0 + oc);
        const float h = tanhf(g_xw[idx]);
        out1[idx] = h;
        const __nv_bfloat16 hi = __float2bfloat16_rn(h);
        const __nv_bfloat16 lo = __float2bfloat16_rn(h - __bfloat162float(hi));
        g_hhi[0][(b0 + ob) * Hdim + c0 + oc] = hi;
        g_hlo[0][(b0 + ob) * Hdim + c0 + oc] = lo;
    }
    unsigned nbar = 0;
    group_barrier(bg, base + (++nbar));

    for (int t = 1; t < Tdim; ++t) {
        const size_t oidx = ((size_t)(b0 + ob) * Tdim + t) * Hdim + (c0 + oc);
        const float xwv = __ldg(&g_xw[oidx]);

        /* stage h3(t-1) hi/lo: [16 b][1024 k] -> padded SMEM */
        const int pp = (t - 1) & 1;
#pragma unroll
        for (int u = 0; u < 8; ++u) {
            const int i = tid + u * RTHREADS;   /* 0..4095 */
            const int arr = i >> 11, rem = i & 2047;
            const int r = rem >> 7, kq = rem & 127;
            const __nv_bfloat16* s = (arr ? g_hlo[pp] : g_hhi[pp]) + (size_t)(b0 + r) * Hdim + kq * 8;
            uint4 v = *(const uint4*)s;
            *(uint4*)(rsm + (arr ? HLO_OFF : HHI_OFF) + (r * SK + kq * 8) * 2) = v;
        }
        __syncthreads();

        /* HMMA: warp w covers k in [64w, 64w+64), 4 n-tiles of 8 */
        float C[4][4];
#pragma unroll
        for (int a = 0; a < 4; ++a)
#pragma unroll
            for (int c = 0; c < 4; ++c) C[a][c] = 0.f;
#pragma unroll
        for (int s = 0; s < 4; ++s) {
            uint32_t ah[4], al[4];
            LDSM_X4(ah, aHiB + s * 32);
            LDSM_X4(al, aLoB + s * 32);
#pragma unroll
            for (int nj = 0; nj < 4; ++nj) {
                uint32_t bh[2], bl[2];
                LDSM_X2(bh, bHiB + nj * (8 * SK * 2) + s * 32);
                LDSM_X2(bl, bLoB + nj * (8 * SK * 2) + s * 32);
                mma16816(C[nj], ah, bh);
                mma16816(C[nj], ah, bl);
                mma16816(C[nj], al, bh);
            }
        }
        __syncthreads();   /* all H reads done: red may alias */

        /* write C frags to reduce buffer */
#pragma unroll
        for (int nj = 0; nj < 4; ++nj) {
            float2 v0, v1;
            v0.x = C[nj][0]; v0.y = C[nj][1];
            v1.x = C[nj][2]; v1.y = C[nj][3];
            *(float2*)&red[w * RWB + g * RST + nj * 8 + 2 * tig] = v0;
            *(float2*)&red[w * RWB + (g + 8) * RST + nj * 8 + 2 * tig] = v1;
        }
        __syncthreads();

        /* reduce 16 k-splits + epilogue */
        float sum = 0.f;
#pragma unroll
        for (int r = 0; r < 16; ++r) sum += red[r * RWB + ob * RST + oc];
        sum += bUs[oc];
        const float h = tanhf(xwv + sum);
        out1[oidx] = h;
        const __nv_bfloat16 hi = __float2bfloat16_rn(h);
        const __nv_bfloat16 lo = __float2bfloat16_rn(h - __bfloat162float(hi));
        g_hhi[t & 1][(b0 + ob) * Hdim + c0 + oc] = hi;
        g_hlo[t & 1][(b0 + ob) * Hdim + c0 + oc] = lo;
        if (t == Tdim - 1) out2[(size_t)(b0 + ob) * Hdim + (c0 + oc)] = h;

        if (t < Tdim - 1) group_barrier(bg, base + (++nbar));
    }
}

/* ================= launch ================= */
extern "C" void kernel_launch(void* const* d_in, const int* in_sizes, int n_in,
                              void* d_out, int out_size)
{
    const float* x  = (const float*)d_in[0];
    const float* W  = (const float*)d_in[1];
    const float* bW = (const float*)d_in[2];
    const float* U  = (const float*)d_in[3];
    const float* bU = (const float*)d_in[4];
    float* out = (float*)d_out;

    cvt_split_kernel<<<8192, 256>>>(x, 0, (int)((size_t)M_TOT * Idim / 4));
    cvt_split_kernel<<<1024, 256>>>(W, 1, (int)((size_t)Hdim * Idim / 4));
    cvt_split_kernel<<<1024, 256>>>(U, 2, (int)((size_t)Hdim * Hdim / 4));

    cudaFuncSetAttribute(gemm_xw_hmma,
                         cudaFuncAttributeMaxDynamicSharedMemorySize, GEMM_SMEM);
    gemm_xw_hmma<<<dim3(Hdim / 128, M_TOT / 128), 256, GEMM_SMEM>>>(bW);

    cudaFuncSetAttribute(rnn_steps_hmma,
                         cudaFuncAttributeMaxDynamicSharedMemorySize, RNN_SMEM);
    rnn_steps_hmma<<<dim3(32, 4), RTHREADS, RNN_SMEM>>>(bU, out);
}